// round 1
// baseline (speedup 1.0000x reference)
#include <cuda_runtime.h>
#include <cstdint>

// Problem constants (fixed by the dataset)
#define NN 131072          // nodes
#define EE 4194304         // edges
#define F1 128             // input feature dim
#define F2 256             // hidden dim
#define SUB 16             // subgraph group size
#define NG (NN / SUB)      // 8192 output rows
#define SCAN_BS 1024
#define NB_SCAN (NN / SCAN_BS)   // 128

// ---------------- device scratch (static, no allocation) ----------------
__device__ int   g_deg[NN];
__device__ float g_dinv[NN];
__device__ int   g_ptr[NN + 1];
__device__ int   g_cursor[NN];
__device__ int   g_csrc[EE];
__device__ float g_cnorm[EE];
__device__ int   g_blockSums[NB_SCAN];
__device__ int   g_edge64;
__device__ float g_bufA[(size_t)NN * F2];   // agg output (layer1 uses first NN*F1)
__device__ float g_bufB[(size_t)NN * F2];   // post-GEMM activations

// ---------------- edge dtype detection ----------------
// int64 node indices < 2^31 => every odd 32-bit word of the array is 0.
__global__ void k_detect(const int* __restrict__ ei32) {
    int found = 0;
    for (int i = threadIdx.x; i < 4096; i += 256) {
        if (ei32[2 * i + 1] != 0) found = 1;
    }
    found = __syncthreads_or(found);
    if (threadIdx.x == 0) g_edge64 = found ? 0 : 1;
}

__device__ __forceinline__ int edge_dst(const void* ei, int e, int is64) {
    if (is64) return (int)((const long long*)ei)[(size_t)EE + e];
    return ((const int*)ei)[(size_t)EE + e];
}
__device__ __forceinline__ int edge_src(const void* ei, int e, int is64) {
    if (is64) return (int)((const long long*)ei)[e];
    return ((const int*)ei)[e];
}

// ---------------- graph normalization / CSR build ----------------
__global__ void k_init_deg() {
    int i = blockIdx.x * blockDim.x + threadIdx.x;
    if (i < NN) g_deg[i] = 1;   // self-loop
}

__global__ void k_count(const void* __restrict__ ei) {
    int e = blockIdx.x * blockDim.x + threadIdx.x;
    if (e >= EE) return;
    int is64 = g_edge64;
    int d = edge_dst(ei, e, is64);
    atomicAdd(&g_deg[d], 1);
}

__global__ void k_dinv() {
    int i = blockIdx.x * blockDim.x + threadIdx.x;
    if (i < NN) g_dinv[i] = rsqrtf((float)g_deg[i]);
}

// exclusive scan of (deg-1) per 1024-node block; local result to g_ptr, totals out
__global__ void k_scan1() {
    __shared__ int sh[2][SCAN_BS];
    int t = threadIdx.x;
    int i = blockIdx.x * SCAN_BS + t;
    int c = g_deg[i] - 1;
    int buf = 0;
    sh[0][t] = c;
    __syncthreads();
#pragma unroll
    for (int off = 1; off < SCAN_BS; off <<= 1) {
        int v = sh[buf][t] + ((t >= off) ? sh[buf][t - off] : 0);
        sh[1 - buf][t] = v;
        buf ^= 1;
        __syncthreads();
    }
    int incl = sh[buf][t];
    g_ptr[i] = incl - c;                        // local exclusive
    if (t == SCAN_BS - 1) g_blockSums[blockIdx.x] = incl;
}

__global__ void k_scan2() {
    __shared__ int sh[2][NB_SCAN];
    int t = threadIdx.x;   // 128 threads
    int c = g_blockSums[t];
    int buf = 0;
    sh[0][t] = c;
    __syncthreads();
#pragma unroll
    for (int off = 1; off < NB_SCAN; off <<= 1) {
        int v = sh[buf][t] + ((t >= off) ? sh[buf][t - off] : 0);
        sh[1 - buf][t] = v;
        buf ^= 1;
        __syncthreads();
    }
    g_blockSums[t] = sh[buf][t] - c;            // exclusive block offsets
}

__global__ void k_scan3() {
    int t = threadIdx.x;
    int i = blockIdx.x * SCAN_BS + t;
    int p = g_ptr[i] + g_blockSums[blockIdx.x];
    g_ptr[i] = p;
    g_cursor[i] = p;
    if (i == 0) g_ptr[NN] = EE;
}

__global__ void k_fill(const void* __restrict__ ei) {
    int e = blockIdx.x * blockDim.x + threadIdx.x;
    if (e >= EE) return;
    int is64 = g_edge64;
    int s = edge_src(ei, e, is64);
    int d = edge_dst(ei, e, is64);
    int pos = atomicAdd(&g_cursor[d], 1);
    g_csrc[pos] = s;
    g_cnorm[pos] = g_dinv[s] * g_dinv[d];
}

// ---------------- aggregation: out[i,:] = sum_{e: dst=i} h[src_e,:]*norm_e + h[i,:]*dinv[i]^2
template <int F>
__global__ void k_agg(const float* __restrict__ h, float* __restrict__ out) {
    int i = blockIdx.x;
    int t = threadIdx.x;
    float di = g_dinv[i];
    float acc = h[(size_t)i * F + t] * di * di;
    int e0 = g_ptr[i], e1 = g_ptr[i + 1];
    __shared__ int   ss[64];
    __shared__ float sn[64];
    for (int base = e0; base < e1; base += 64) {
        int cnt = min(64, e1 - base);
        if (t < cnt) {
            ss[t] = g_csrc[base + t];
            sn[t] = g_cnorm[base + t];
        }
        __syncthreads();
        int j = 0;
        for (; j + 4 <= cnt; j += 4) {
            float v0 = h[(size_t)ss[j + 0] * F + t];
            float v1 = h[(size_t)ss[j + 1] * F + t];
            float v2 = h[(size_t)ss[j + 2] * F + t];
            float v3 = h[(size_t)ss[j + 3] * F + t];
            acc += v0 * sn[j + 0];
            acc += v1 * sn[j + 1];
            acc += v2 * sn[j + 2];
            acc += v3 * sn[j + 3];
        }
        for (; j < cnt; j++)
            acc += h[(size_t)ss[j] * F + t] * sn[j];
        __syncthreads();
    }
    out[(size_t)i * F + t] = acc;
}

__global__ void k_agg1(const float* __restrict__ x) { /* unused wrapper removed */ }

// ---------------- GEMM: out = relu(A @ W + b), A=[M,K], W=[K,256], out=[M,256]
// 128x128 tile, 256 threads, 8x8 per thread, TK=16
template <int K>
__global__ void __launch_bounds__(256)
k_gemm(const float* __restrict__ A, const float* __restrict__ W,
       const float* __restrict__ bias, float* __restrict__ out) {
    const int BM = 128, BN = 128, TK = 16, NC = F2;
    __shared__ float Ast[TK][BM];
    __shared__ float Bs[TK][BN];
    int tid = threadIdx.x;
    int tx = tid & 15;        // 0..15
    int ty = tid >> 4;        // 0..15
    int m0 = blockIdx.y * BM;
    int n0 = blockIdx.x * BN;

    float acc[8][8];
#pragma unroll
    for (int i = 0; i < 8; i++)
#pragma unroll
        for (int j = 0; j < 8; j++) acc[i][j] = 0.0f;

    for (int k0 = 0; k0 < K; k0 += TK) {
#pragma unroll
        for (int it = 0; it < 8; it++) {
            int flat = tid + it * 256;         // over BM*TK = 2048
            int m = flat >> 4;
            int kk = flat & 15;
            Ast[kk][m] = A[(size_t)(m0 + m) * K + k0 + kk];
        }
#pragma unroll
        for (int it = 0; it < 8; it++) {
            int flat = tid + it * 256;         // over TK*BN = 2048
            int kk = flat >> 7;
            int n = flat & 127;
            Bs[kk][n] = W[(size_t)(k0 + kk) * NC + n0 + n];
        }
        __syncthreads();
#pragma unroll
        for (int kk = 0; kk < TK; kk++) {
            float a[8], b[8];
            const float4* ap = reinterpret_cast<const float4*>(&Ast[kk][ty * 8]);
            const float4* bp = reinterpret_cast<const float4*>(&Bs[kk][tx * 8]);
            float4 a0 = ap[0], a1 = ap[1];
            float4 b0 = bp[0], b1 = bp[1];
            a[0]=a0.x; a[1]=a0.y; a[2]=a0.z; a[3]=a0.w;
            a[4]=a1.x; a[5]=a1.y; a[6]=a1.z; a[7]=a1.w;
            b[0]=b0.x; b[1]=b0.y; b[2]=b0.z; b[3]=b0.w;
            b[4]=b1.x; b[5]=b1.y; b[6]=b1.z; b[7]=b1.w;
#pragma unroll
            for (int i = 0; i < 8; i++)
#pragma unroll
                for (int j = 0; j < 8; j++)
                    acc[i][j] = fmaf(a[i], b[j], acc[i][j]);
        }
        __syncthreads();
    }
    // epilogue: bias + relu
#pragma unroll
    for (int i = 0; i < 8; i++) {
        size_t row = (size_t)(m0 + ty * 8 + i) * NC + n0 + tx * 8;
#pragma unroll
        for (int j = 0; j < 8; j++) {
            float v = acc[i][j] + bias[n0 + tx * 8 + j];
            out[row + j] = fmaxf(v, 0.0f);
        }
    }
}

// ---------------- output head: out[g] = dot(h2[g*4096 : +4096], Wout) + bout
__global__ void k_out(const float* __restrict__ h2, const float* __restrict__ Wout,
                      const float* __restrict__ bout, float* __restrict__ out) {
    int g = blockIdx.x;
    int t = threadIdx.x;
    const float4* hp = reinterpret_cast<const float4*>(h2 + (size_t)g * (SUB * F2));
    const float4* wp = reinterpret_cast<const float4*>(Wout);
    float s = 0.0f;
    for (int j = t; j < (SUB * F2) / 4; j += 256) {
        float4 hv = hp[j];
        float4 wv = wp[j];
        s += hv.x * wv.x + hv.y * wv.y + hv.z * wv.z + hv.w * wv.w;
    }
    // warp reduce
#pragma unroll
    for (int off = 16; off > 0; off >>= 1)
        s += __shfl_down_sync(0xFFFFFFFF, s, off);
    __shared__ float sh[8];
    if ((t & 31) == 0) sh[t >> 5] = s;
    __syncthreads();
    if (t < 8) {
        float v = sh[t];
#pragma unroll
        for (int off = 4; off > 0; off >>= 1)
            v += __shfl_down_sync(0xFF, v, off);
        if (t == 0) out[g] = v + bout[0];
    }
}

// ---------------- launch ----------------
extern "C" void kernel_launch(void* const* d_in, const int* in_sizes, int n_in,
                              void* d_out, int out_size) {
    const float* x    = (const float*)d_in[0];
    const void*  ei   = d_in[1];
    const float* W1   = (const float*)d_in[2];
    const float* b1   = (const float*)d_in[3];
    const float* W2   = (const float*)d_in[4];
    const float* b2   = (const float*)d_in[5];
    const float* Wout = (const float*)d_in[6];
    const float* bout = (const float*)d_in[7];
    float* out = (float*)d_out;

    // device-global pointers via mapped symbols is forbidden-free: kernels use
    // globals directly; only host-visible pointers passed are harness buffers.
    k_detect<<<1, 256>>>((const int*)ei);
    k_init_deg<<<NN / 256, 256>>>();
    k_count<<<EE / 256, 256>>>(ei);
    k_dinv<<<NN / 256, 256>>>();
    k_scan1<<<NB_SCAN, SCAN_BS>>>();
    k_scan2<<<1, NB_SCAN>>>();
    k_scan3<<<NB_SCAN, SCAN_BS>>>();
    k_fill<<<EE / 256, 256>>>(ei);

    // layer 1: aggregate-first (128-wide) then GEMM(128->256) + relu
    {
        float* bufA;  cudaGetSymbolAddress((void**)&bufA, g_bufA);
        float* bufB;  cudaGetSymbolAddress((void**)&bufB, g_bufB);
        k_agg<F1><<<NN, F1>>>(x, bufA);
        dim3 grid1(F2 / 128, NN / 128);
        k_gemm<F1><<<grid1, 256>>>(bufA, W1, b1, bufB);
        // layer 2: aggregate 256-wide then GEMM(256->256) + relu
        k_agg<F2><<<NN, F2>>>(bufB, bufA);
        dim3 grid2(F2 / 128, NN / 128);
        k_gemm<F2><<<grid2, 256>>>(bufA, W2, b2, bufB);
        // output head
        k_out<<<NG, 256>>>(bufB, Wout, bout, out);
    }
}

// round 3
// speedup vs baseline: 1.5087x; 1.5087x over previous
#include <cuda_runtime.h>
#include <cstdint>

// Problem constants (fixed by the dataset)
#define NN 131072          // nodes
#define EE 4194304         // edges
#define F1 128             // input feature dim
#define F2 256             // hidden dim
#define SUB 16             // subgraph group size
#define NG (NN / SUB)      // 8192 output rows
#define SCAN_BS 1024
#define NB_SCAN (NN / SCAN_BS)   // 128

// ---------------- device scratch (static, no allocation) ----------------
__device__ int   g_deg[NN];
__device__ float g_dinv[NN];
__device__ int   g_ptr[NN + 1];
__device__ int   g_cursor[NN];
__device__ int   g_csrc[EE];
__device__ float g_cnorm[EE];
__device__ int   g_blockSums[NB_SCAN];
__device__ int   g_edge64;
__device__ float g_bufA[(size_t)NN * F2];   // agg output
__device__ float g_bufB[(size_t)NN * F2];   // post-GEMM activations
__device__ float g_W1t[(size_t)F2 * F1];    // W1^T, tf32-rounded  [256 x 128]
__device__ float g_W2t[(size_t)F2 * F2];    // W2^T, tf32-rounded  [256 x 256]

__device__ __forceinline__ float round_tf32(float f) {
    uint32_t u;
    asm("cvt.rna.tf32.f32 %0, %1;" : "=r"(u) : "f"(f));
    return __uint_as_float(u);
}

// mma.sync m16n8k8 tf32 (generic PTX, sm_80+; legal under compute_103)
__device__ __forceinline__ void mma_tf32(float* c, const uint32_t* a, const uint32_t* b) {
    asm volatile(
        "mma.sync.aligned.m16n8k8.row.col.f32.tf32.tf32.f32 "
        "{%0,%1,%2,%3}, {%4,%5,%6,%7}, {%8,%9}, {%0,%1,%2,%3};"
        : "+f"(c[0]), "+f"(c[1]), "+f"(c[2]), "+f"(c[3])
        : "r"(a[0]), "r"(a[1]), "r"(a[2]), "r"(a[3]),
          "r"(b[0]), "r"(b[1]));
}

// ---------------- edge dtype detection ----------------
// int64 node indices < 2^31 => every odd 32-bit word of the array is 0.
__global__ void k_detect(const int* __restrict__ ei32) {
    int found = 0;
    for (int i = threadIdx.x; i < 4096; i += 256)
        if (ei32[2 * i + 1] != 0) found = 1;
    found = __syncthreads_or(found);
    if (threadIdx.x == 0) g_edge64 = found ? 0 : 1;
}

__device__ __forceinline__ int edge_dst(const void* ei, int e, int is64) {
    if (is64) return (int)((const long long*)ei)[(size_t)EE + e];
    return ((const int*)ei)[(size_t)EE + e];
}
__device__ __forceinline__ int edge_src(const void* ei, int e, int is64) {
    if (is64) return (int)((const long long*)ei)[e];
    return ((const int*)ei)[e];
}

// ---------------- graph normalization / CSR build ----------------
__global__ void k_init_deg() {
    int i = blockIdx.x * blockDim.x + threadIdx.x;
    if (i < NN) g_deg[i] = 1;
}

__global__ void k_count(const void* __restrict__ ei) {
    int e = blockIdx.x * blockDim.x + threadIdx.x;
    if (e >= EE) return;
    atomicAdd(&g_deg[edge_dst(ei, e, g_edge64)], 1);
}

__global__ void k_dinv() {
    int i = blockIdx.x * blockDim.x + threadIdx.x;
    if (i < NN) g_dinv[i] = rsqrtf((float)g_deg[i]);
}

__global__ void k_scan1() {
    __shared__ int sh[2][SCAN_BS];
    int t = threadIdx.x;
    int i = blockIdx.x * SCAN_BS + t;
    int c = g_deg[i] - 1;
    int buf = 0;
    sh[0][t] = c;
    __syncthreads();
#pragma unroll
    for (int off = 1; off < SCAN_BS; off <<= 1) {
        int v = sh[buf][t] + ((t >= off) ? sh[buf][t - off] : 0);
        sh[1 - buf][t] = v;
        buf ^= 1;
        __syncthreads();
    }
    int incl = sh[buf][t];
    g_ptr[i] = incl - c;
    if (t == SCAN_BS - 1) g_blockSums[blockIdx.x] = incl;
}

__global__ void k_scan2() {
    __shared__ int sh[2][NB_SCAN];
    int t = threadIdx.x;
    int c = g_blockSums[t];
    int buf = 0;
    sh[0][t] = c;
    __syncthreads();
#pragma unroll
    for (int off = 1; off < NB_SCAN; off <<= 1) {
        int v = sh[buf][t] + ((t >= off) ? sh[buf][t - off] : 0);
        sh[1 - buf][t] = v;
        buf ^= 1;
        __syncthreads();
    }
    g_blockSums[t] = sh[buf][t] - c;
}

__global__ void k_scan3() {
    int t = threadIdx.x;
    int i = blockIdx.x * SCAN_BS + t;
    int p = g_ptr[i] + g_blockSums[blockIdx.x];
    g_ptr[i] = p;
    g_cursor[i] = p;
    if (i == 0) g_ptr[NN] = EE;
}

__global__ void k_fill(const void* __restrict__ ei) {
    int e = blockIdx.x * blockDim.x + threadIdx.x;
    if (e >= EE) return;
    int is64 = g_edge64;
    int s = edge_src(ei, e, is64);
    int d = edge_dst(ei, e, is64);
    int pos = atomicAdd(&g_cursor[d], 1);
    g_csrc[pos] = s;
    g_cnorm[pos] = g_dinv[s] * g_dinv[d];
}

// ---------------- aggregation ----------------
template <int F>
__global__ void k_agg(const float* __restrict__ h, float* __restrict__ out) {
    int i = blockIdx.x;
    int t = threadIdx.x;
    float di = g_dinv[i];
    float acc = h[(size_t)i * F + t] * di * di;
    int e0 = g_ptr[i], e1 = g_ptr[i + 1];
    __shared__ int   ss[64];
    __shared__ float sn[64];
    for (int base = e0; base < e1; base += 64) {
        int cnt = min(64, e1 - base);
        if (t < cnt) {
            ss[t] = g_csrc[base + t];
            sn[t] = g_cnorm[base + t];
        }
        __syncthreads();
        int j = 0;
        for (; j + 4 <= cnt; j += 4) {
            float v0 = h[(size_t)ss[j + 0] * F + t];
            float v1 = h[(size_t)ss[j + 1] * F + t];
            float v2 = h[(size_t)ss[j + 2] * F + t];
            float v3 = h[(size_t)ss[j + 3] * F + t];
            acc += v0 * sn[j + 0];
            acc += v1 * sn[j + 1];
            acc += v2 * sn[j + 2];
            acc += v3 * sn[j + 3];
        }
        for (; j < cnt; j++)
            acc += h[(size_t)ss[j] * F + t] * sn[j];
        __syncthreads();
    }
    out[(size_t)i * F + t] = acc;
}

// ---------------- weight transpose + tf32 rounding ----------------
// W [K, 256] row-major -> Wt [256, K] row-major, tf32-rounded
template <int K>
__global__ void k_wt(const float* __restrict__ W, float* __restrict__ Wt) {
    int idx = blockIdx.x * blockDim.x + threadIdx.x;   // over K*256
    if (idx >= K * 256) return;
    int k = idx / 256, n = idx % 256;
    Wt[(size_t)n * K + k] = round_tf32(W[idx]);
}

// ---------------- tf32 mma.sync GEMM ----------------
// out[M,256] = relu(A[M,K] @ Wt^T + bias), Wt is [256, K] (i.e. B col-major)
// CTA: 256 threads, BM=128, BN=128, BK=32. Warp grid 4(M) x 2(N); each warp
// computes 32x64 via m16n8k8 frags (2 M-tiles x 8 N-tiles x 4 k-steps).
template <int K>
__global__ void __launch_bounds__(256)
k_gemm_mma(const float* __restrict__ A, const float* __restrict__ Wt,
           const float* __restrict__ bias, float* __restrict__ out) {
    const int BM = 128, BN = 128, BK = 32, LD = BK + 4;   // pad -> conflict-free frags
    __shared__ float As[BM][LD];
    __shared__ float Bs[BN][LD];

    int tid = threadIdx.x;
    int lane = tid & 31;
    int warp = tid >> 5;
    int warp_m = warp & 3;       // 0..3
    int warp_n = warp >> 2;      // 0..1
    int gid = lane >> 2;         // 0..7
    int tig = lane & 3;          // 0..3
    int m0 = blockIdx.y * BM;
    int n0 = blockIdx.x * BN;

    float c[2][8][4];
#pragma unroll
    for (int mm = 0; mm < 2; mm++)
#pragma unroll
        for (int nn = 0; nn < 8; nn++)
#pragma unroll
            for (int q = 0; q < 4; q++) c[mm][nn][q] = 0.0f;

    for (int k0 = 0; k0 < K; k0 += BK) {
        // stage A: 128 rows x 32 floats = 1024 float4, tf32-round on the fly
#pragma unroll
        for (int it = 0; it < 4; it++) {
            int i = tid + it * 256;
            int row = i >> 3, c4 = i & 7;
            float4 v = *(const float4*)&A[(size_t)(m0 + row) * K + k0 + c4 * 4];
            v.x = round_tf32(v.x); v.y = round_tf32(v.y);
            v.z = round_tf32(v.z); v.w = round_tf32(v.w);
            *(float4*)&As[row][c4 * 4] = v;
        }
        // stage B: 128 rows (n) x 32 floats (k), already tf32-rounded
#pragma unroll
        for (int it = 0; it < 4; it++) {
            int i = tid + it * 256;
            int row = i >> 3, c4 = i & 7;
            *(float4*)&Bs[row][c4 * 4] =
                *(const float4*)&Wt[(size_t)(n0 + row) * K + k0 + c4 * 4];
        }
        __syncthreads();

#pragma unroll
        for (int kk = 0; kk < 4; kk++) {
            int kb = kk * 8;
            uint32_t a[2][4], b[8][2];
#pragma unroll
            for (int mm = 0; mm < 2; mm++) {
                int r = warp_m * 32 + mm * 16;
                a[mm][0] = __float_as_uint(As[r + gid    ][kb + tig    ]);
                a[mm][1] = __float_as_uint(As[r + gid + 8][kb + tig    ]);
                a[mm][2] = __float_as_uint(As[r + gid    ][kb + tig + 4]);
                a[mm][3] = __float_as_uint(As[r + gid + 8][kb + tig + 4]);
            }
#pragma unroll
            for (int nn = 0; nn < 8; nn++) {
                int r = warp_n * 64 + nn * 8;
                b[nn][0] = __float_as_uint(Bs[r + gid][kb + tig    ]);
                b[nn][1] = __float_as_uint(Bs[r + gid][kb + tig + 4]);
            }
#pragma unroll
            for (int mm = 0; mm < 2; mm++)
#pragma unroll
                for (int nn = 0; nn < 8; nn++)
                    mma_tf32(c[mm][nn], a[mm], b[nn]);
        }
        __syncthreads();
    }

    // epilogue: bias + relu, float2 stores
#pragma unroll
    for (int mm = 0; mm < 2; mm++) {
        int rbase = m0 + warp_m * 32 + mm * 16;
#pragma unroll
        for (int nn = 0; nn < 8; nn++) {
            int col = n0 + warp_n * 64 + nn * 8 + tig * 2;
            float bi0 = bias[col], bi1 = bias[col + 1];
            float2 o0, o1;
            o0.x = fmaxf(c[mm][nn][0] + bi0, 0.0f);
            o0.y = fmaxf(c[mm][nn][1] + bi1, 0.0f);
            o1.x = fmaxf(c[mm][nn][2] + bi0, 0.0f);
            o1.y = fmaxf(c[mm][nn][3] + bi1, 0.0f);
            *(float2*)&out[(size_t)(rbase + gid    ) * F2 + col] = o0;
            *(float2*)&out[(size_t)(rbase + gid + 8) * F2 + col] = o1;
        }
    }
}

// ---------------- output head ----------------
__global__ void k_out(const float* __restrict__ h2, const float* __restrict__ Wout,
                      const float* __restrict__ bout, float* __restrict__ out) {
    int g = blockIdx.x;
    int t = threadIdx.x;
    const float4* hp = reinterpret_cast<const float4*>(h2 + (size_t)g * (SUB * F2));
    const float4* wp = reinterpret_cast<const float4*>(Wout);
    float s = 0.0f;
    for (int j = t; j < (SUB * F2) / 4; j += 256) {
        float4 hv = hp[j];
        float4 wv = wp[j];
        s += hv.x * wv.x + hv.y * wv.y + hv.z * wv.z + hv.w * wv.w;
    }
#pragma unroll
    for (int off = 16; off > 0; off >>= 1)
        s += __shfl_down_sync(0xFFFFFFFF, s, off);
    __shared__ float sh[8];
    if ((t & 31) == 0) sh[t >> 5] = s;
    __syncthreads();
    if (t < 8) {
        float v = sh[t];
#pragma unroll
        for (int off = 4; off > 0; off >>= 1)
            v += __shfl_down_sync(0xFF, v, off);
        if (t == 0) out[g] = v + bout[0];
    }
}

// ---------------- launch ----------------
extern "C" void kernel_launch(void* const* d_in, const int* in_sizes, int n_in,
                              void* d_out, int out_size) {
    const float* x    = (const float*)d_in[0];
    const void*  ei   = d_in[1];
    const float* W1   = (const float*)d_in[2];
    const float* b1   = (const float*)d_in[3];
    const float* W2   = (const float*)d_in[4];
    const float* b2   = (const float*)d_in[5];
    const float* Wout = (const float*)d_in[6];
    const float* bout = (const float*)d_in[7];
    float* out = (float*)d_out;

    float *bufA, *bufB, *w1t, *w2t;
    cudaGetSymbolAddress((void**)&bufA, g_bufA);
    cudaGetSymbolAddress((void**)&bufB, g_bufB);
    cudaGetSymbolAddress((void**)&w1t, g_W1t);
    cudaGetSymbolAddress((void**)&w2t, g_W2t);

    // graph build
    k_detect<<<1, 256>>>((const int*)ei);
    k_init_deg<<<NN / 256, 256>>>();
    k_count<<<EE / 256, 256>>>(ei);
    k_dinv<<<NN / 256, 256>>>();
    k_scan1<<<NB_SCAN, SCAN_BS>>>();
    k_scan2<<<1, NB_SCAN>>>();
    k_scan3<<<NB_SCAN, SCAN_BS>>>();
    k_fill<<<EE / 256, 256>>>(ei);

    // weight prep (transpose + tf32 round)
    k_wt<F1><<<(F1 * 256 + 255) / 256, 256>>>(W1, w1t);
    k_wt<F2><<<(F2 * 256 + 255) / 256, 256>>>(W2, w2t);

    // layer 1: aggregate-first (128-wide) then mma-GEMM(128->256) + relu
    k_agg<F1><<<NN, F1>>>(x, bufA);
    {
        dim3 grid(F2 / 128, NN / 128);
        k_gemm_mma<F1><<<grid, 256>>>(bufA, w1t, b1, bufB);
    }
    // layer 2: aggregate 256-wide then mma-GEMM(256->256) + relu
    k_agg<F2><<<NN, F2>>>(bufB, bufA);
    {
        dim3 grid(F2 / 128, NN / 128);
        k_gemm_mma<F2><<<grid, 256>>>(bufA, w2t, b2, bufB);
    }
    // output head
    k_out<<<NG, 256>>>(bufB, Wout, bout, out);
}

// round 4
// speedup vs baseline: 2.3820x; 1.5788x over previous
#include <cuda_runtime.h>
#include <cuda_fp16.h>
#include <cstdint>

// Problem constants (fixed by the dataset)
#define NN 131072          // nodes
#define EE 4194304         // edges
#define F1 128             // input feature dim
#define F2 256             // hidden dim
#define SUB 16             // subgraph group size
#define NG (NN / SUB)      // 8192 output rows
#define SCAN_BS 1024
#define NB_SCAN (NN / SCAN_BS)   // 128

// ---------------- device scratch (static, no allocation) ----------------
__device__ int    g_deg[NN];
__device__ float  g_dinv[NN];
__device__ int    g_ptr[NN + 1];
__device__ int    g_cursor[NN];
__device__ int    g_csrc[EE];
__device__ float  g_cnorm[EE];
__device__ int    g_blockSums[NB_SCAN];
__device__ int    g_edge64;
__device__ float  g_bufA[(size_t)NN * F2];   // agg output (tf32-rounded fp32)
__device__ float  g_bufB[(size_t)NN * F2];   // final layer-2 activations (fp32)
__device__ __half g_x16[(size_t)NN * F1];    // x in fp16
__device__ __half g_h16[(size_t)NN * F2];    // h1 in fp16
__device__ float  g_W1t[(size_t)F2 * F1];    // W1^T, tf32-rounded  [256 x 128]
__device__ float  g_W2t[(size_t)F2 * F2];    // W2^T, tf32-rounded  [256 x 256]

__device__ __forceinline__ float round_tf32(float f) {
    uint32_t u;
    asm("cvt.rna.tf32.f32 %0, %1;" : "=r"(u) : "f"(f));
    return __uint_as_float(u);
}

__device__ __forceinline__ uint32_t smem_u32(const void* p) {
    return (uint32_t)__cvta_generic_to_shared(p);
}

__device__ __forceinline__ void cp16(uint32_t smem_dst, const void* gsrc) {
    asm volatile("cp.async.cg.shared.global [%0], [%1], 16;"
                 :: "r"(smem_dst), "l"(gsrc));
}
__device__ __forceinline__ void cp_commit() {
    asm volatile("cp.async.commit_group;");
}
template <int N>
__device__ __forceinline__ void cp_wait() {
    asm volatile("cp.async.wait_group %0;" :: "n"(N));
}

// mma.sync m16n8k8 tf32 (generic PTX, sm_80+; legal under compute_103)
__device__ __forceinline__ void mma_tf32(float* c, const uint32_t* a, const uint32_t* b) {
    asm volatile(
        "mma.sync.aligned.m16n8k8.row.col.f32.tf32.tf32.f32 "
        "{%0,%1,%2,%3}, {%4,%5,%6,%7}, {%8,%9}, {%0,%1,%2,%3};"
        : "+f"(c[0]), "+f"(c[1]), "+f"(c[2]), "+f"(c[3])
        : "r"(a[0]), "r"(a[1]), "r"(a[2]), "r"(a[3]),
          "r"(b[0]), "r"(b[1]));
}

// ---------------- edge dtype detection ----------------
// int64 node indices < 2^31 => every odd 32-bit word of the array is 0.
__global__ void k_detect(const int* __restrict__ ei32) {
    int found = 0;
    for (int i = threadIdx.x; i < 4096; i += 256)
        if (ei32[2 * i + 1] != 0) found = 1;
    found = __syncthreads_or(found);
    if (threadIdx.x == 0) g_edge64 = found ? 0 : 1;
}

__device__ __forceinline__ int edge_dst(const void* ei, int e, int is64) {
    if (is64) return (int)((const long long*)ei)[(size_t)EE + e];
    return ((const int*)ei)[(size_t)EE + e];
}
__device__ __forceinline__ int edge_src(const void* ei, int e, int is64) {
    if (is64) return (int)((const long long*)ei)[e];
    return ((const int*)ei)[e];
}

// ---------------- graph normalization / CSR build ----------------
__global__ void k_init_deg() {
    int i = blockIdx.x * blockDim.x + threadIdx.x;
    if (i < NN) g_deg[i] = 1;
}

__global__ void k_count(const void* __restrict__ ei) {
    int e = blockIdx.x * blockDim.x + threadIdx.x;
    if (e >= EE) return;
    atomicAdd(&g_deg[edge_dst(ei, e, g_edge64)], 1);
}

__global__ void k_dinv() {
    int i = blockIdx.x * blockDim.x + threadIdx.x;
    if (i < NN) g_dinv[i] = rsqrtf((float)g_deg[i]);
}

__global__ void k_scan1() {
    __shared__ int sh[2][SCAN_BS];
    int t = threadIdx.x;
    int i = blockIdx.x * SCAN_BS + t;
    int c = g_deg[i] - 1;
    int buf = 0;
    sh[0][t] = c;
    __syncthreads();
#pragma unroll
    for (int off = 1; off < SCAN_BS; off <<= 1) {
        int v = sh[buf][t] + ((t >= off) ? sh[buf][t - off] : 0);
        sh[1 - buf][t] = v;
        buf ^= 1;
        __syncthreads();
    }
    int incl = sh[buf][t];
    g_ptr[i] = incl - c;
    if (t == SCAN_BS - 1) g_blockSums[blockIdx.x] = incl;
}

__global__ void k_scan2() {
    __shared__ int sh[2][NB_SCAN];
    int t = threadIdx.x;
    int c = g_blockSums[t];
    int buf = 0;
    sh[0][t] = c;
    __syncthreads();
#pragma unroll
    for (int off = 1; off < NB_SCAN; off <<= 1) {
        int v = sh[buf][t] + ((t >= off) ? sh[buf][t - off] : 0);
        sh[1 - buf][t] = v;
        buf ^= 1;
        __syncthreads();
    }
    g_blockSums[t] = sh[buf][t] - c;
}

__global__ void k_scan3() {
    int t = threadIdx.x;
    int i = blockIdx.x * SCAN_BS + t;
    int p = g_ptr[i] + g_blockSums[blockIdx.x];
    g_ptr[i] = p;
    g_cursor[i] = p;
    if (i == 0) g_ptr[NN] = EE;
}

__global__ void k_fill(const void* __restrict__ ei) {
    int e = blockIdx.x * blockDim.x + threadIdx.x;
    if (e >= EE) return;
    int is64 = g_edge64;
    int s = edge_src(ei, e, is64);
    int d = edge_dst(ei, e, is64);
    int pos = atomicAdd(&g_cursor[d], 1);
    g_csrc[pos] = s;
    g_cnorm[pos] = g_dinv[s] * g_dinv[d];
}

// ---------------- fp32 -> fp16 conversion (vectorized) ----------------
__global__ void k_f2h(const float* __restrict__ src, __half* __restrict__ dst, int n4) {
    int i = blockIdx.x * blockDim.x + threadIdx.x;   // over n/4
    if (i >= n4) return;
    float4 v = ((const float4*)src)[i];
    __half2 h0 = __floats2half2_rn(v.x, v.y);
    __half2 h1 = __floats2half2_rn(v.z, v.w);
    ((__half2*)dst)[2 * i    ] = h0;
    ((__half2*)dst)[2 * i + 1] = h1;
}

// ---------------- aggregation on fp16 features, fp32 accumulate ----------------
// out[i,:] = tf32_round( sum_{e: dst=i} h[src_e,:]*norm_e + h[i,:]*dinv[i]^2 )
// blockDim = F/2 threads, each owns one half2 column pair.
template <int F>
__global__ void k_agg_h(const __half* __restrict__ h, float* __restrict__ outp) {
    const int T = F / 2;
    int i = blockIdx.x;
    int t = threadIdx.x;
    const __half2* hp = (const __half2*)h;
    float di = g_dinv[i];
    float2 self = __half22float2(hp[(size_t)i * T + t]);
    float ax = self.x * di * di;
    float ay = self.y * di * di;
    int e0 = g_ptr[i], e1 = g_ptr[i + 1];
    __shared__ int   ss[64];
    __shared__ float sn[64];
    for (int base = e0; base < e1; base += 64) {
        int cnt = min(64, e1 - base);
        if (t < cnt) {
            ss[t] = g_csrc[base + t];
            sn[t] = g_cnorm[base + t];
        }
        __syncthreads();
        int j = 0;
        for (; j + 4 <= cnt; j += 4) {
            __half2 v0 = hp[(size_t)ss[j + 0] * T + t];
            __half2 v1 = hp[(size_t)ss[j + 1] * T + t];
            __half2 v2 = hp[(size_t)ss[j + 2] * T + t];
            __half2 v3 = hp[(size_t)ss[j + 3] * T + t];
            float2 f0 = __half22float2(v0);
            float2 f1 = __half22float2(v1);
            float2 f2 = __half22float2(v2);
            float2 f3 = __half22float2(v3);
            ax = fmaf(f0.x, sn[j + 0], ax); ay = fmaf(f0.y, sn[j + 0], ay);
            ax = fmaf(f1.x, sn[j + 1], ax); ay = fmaf(f1.y, sn[j + 1], ay);
            ax = fmaf(f2.x, sn[j + 2], ax); ay = fmaf(f2.y, sn[j + 2], ay);
            ax = fmaf(f3.x, sn[j + 3], ax); ay = fmaf(f3.y, sn[j + 3], ay);
        }
        for (; j < cnt; j++) {
            float2 f = __half22float2(hp[(size_t)ss[j] * T + t]);
            ax = fmaf(f.x, sn[j], ax);
            ay = fmaf(f.y, sn[j], ay);
        }
        __syncthreads();
    }
    float2 o;
    o.x = round_tf32(ax);
    o.y = round_tf32(ay);
    *(float2*)&outp[(size_t)i * F + 2 * t] = o;
}

// ---------------- weight transpose + tf32 rounding ----------------
// W [K, 256] row-major -> Wt [256, K] row-major, tf32-rounded
template <int K>
__global__ void k_wt(const float* __restrict__ W, float* __restrict__ Wt) {
    int idx = blockIdx.x * blockDim.x + threadIdx.x;   // over K*256
    if (idx >= K * 256) return;
    int k = idx / 256, n = idx % 256;
    Wt[(size_t)n * K + k] = round_tf32(W[idx]);
}

// ---------------- tf32 mma.sync GEMM, cp.async double-buffered ----------------
// out[M,256] = relu(A[M,K] @ Wt^T + bias); A already tf32-rounded; Wt [256,K].
// CTA: 256 threads, BM=128, BN=128, BK=16, 2 stages. Warp grid 4(M) x 2(N).
template <int K, typename OutT>
__global__ void __launch_bounds__(256)
k_gemm_mma(const float* __restrict__ A, const float* __restrict__ Wt,
           const float* __restrict__ bias, OutT* __restrict__ out) {
    const int BK = 16, LD = BK + 4;   // LD=20: frag loads conflict-free
    __shared__ float As[2][128][LD];
    __shared__ float Bs[2][128][LD];

    int tid = threadIdx.x;
    int lane = tid & 31;
    int warp = tid >> 5;
    int warp_m = warp & 3;       // 0..3
    int warp_n = warp >> 2;      // 0..1
    int gid = lane >> 2;         // 0..7
    int tig = lane & 3;          // 0..3
    int m0 = blockIdx.y * 128;
    int n0 = blockIdx.x * 128;

    float c[2][8][4];
#pragma unroll
    for (int mm = 0; mm < 2; mm++)
#pragma unroll
        for (int nn = 0; nn < 8; nn++)
#pragma unroll
            for (int q = 0; q < 4; q++) c[mm][nn][q] = 0.0f;

    // staging: 128 rows x 4 float4 per tile = 512 cp16; 2 per thread per tile
    int srow0 = tid >> 2, sc0 = (tid & 3) * 4;            // i = tid
    int srow1 = (tid + 256) >> 2, sc1 = sc0;              // i = tid+256 (same c4)
    const int NCH = K / BK;

    {   // prefetch chunk 0 into buf 0
        cp16(smem_u32(&As[0][srow0][sc0]), &A[(size_t)(m0 + srow0) * K + sc0]);
        cp16(smem_u32(&Bs[0][srow0][sc0]), &Wt[(size_t)(n0 + srow0) * K + sc0]);
        cp16(smem_u32(&As[0][srow1][sc1]), &A[(size_t)(m0 + srow1) * K + sc1]);
        cp16(smem_u32(&Bs[0][srow1][sc1]), &Wt[(size_t)(n0 + srow1) * K + sc1]);
        cp_commit();
    }

#pragma unroll
    for (int ch = 0; ch < NCH; ch++) {
        int buf = ch & 1;
        if (ch + 1 < NCH) {
            int nb = buf ^ 1, kofs = (ch + 1) * BK;
            cp16(smem_u32(&As[nb][srow0][sc0]), &A[(size_t)(m0 + srow0) * K + kofs + sc0]);
            cp16(smem_u32(&Bs[nb][srow0][sc0]), &Wt[(size_t)(n0 + srow0) * K + kofs + sc0]);
            cp16(smem_u32(&As[nb][srow1][sc1]), &A[(size_t)(m0 + srow1) * K + kofs + sc1]);
            cp16(smem_u32(&Bs[nb][srow1][sc1]), &Wt[(size_t)(n0 + srow1) * K + kofs + sc1]);
        }
        cp_commit();
        cp_wait<1>();
        __syncthreads();

#pragma unroll
        for (int kk = 0; kk < 2; kk++) {
            int kb = kk * 8;
            uint32_t a[2][4], b[8][2];
#pragma unroll
            for (int mm = 0; mm < 2; mm++) {
                int r = warp_m * 32 + mm * 16;
                a[mm][0] = __float_as_uint(As[buf][r + gid    ][kb + tig    ]);
                a[mm][1] = __float_as_uint(As[buf][r + gid + 8][kb + tig    ]);
                a[mm][2] = __float_as_uint(As[buf][r + gid    ][kb + tig + 4]);
                a[mm][3] = __float_as_uint(As[buf][r + gid + 8][kb + tig + 4]);
            }
#pragma unroll
            for (int nn = 0; nn < 8; nn++) {
                int r = warp_n * 64 + nn * 8;
                b[nn][0] = __float_as_uint(Bs[buf][r + gid][kb + tig    ]);
                b[nn][1] = __float_as_uint(Bs[buf][r + gid][kb + tig + 4]);
            }
#pragma unroll
            for (int mm = 0; mm < 2; mm++)
#pragma unroll
                for (int nn = 0; nn < 8; nn++)
                    mma_tf32(c[mm][nn], a[mm], b[nn]);
        }
        __syncthreads();
    }

    // epilogue: bias + relu
#pragma unroll
    for (int mm = 0; mm < 2; mm++) {
        int rbase = m0 + warp_m * 32 + mm * 16;
#pragma unroll
        for (int nn = 0; nn < 8; nn++) {
            int col = n0 + warp_n * 64 + nn * 8 + tig * 2;
            float bi0 = bias[col], bi1 = bias[col + 1];
            float v00 = fmaxf(c[mm][nn][0] + bi0, 0.0f);
            float v01 = fmaxf(c[mm][nn][1] + bi1, 0.0f);
            float v10 = fmaxf(c[mm][nn][2] + bi0, 0.0f);
            float v11 = fmaxf(c[mm][nn][3] + bi1, 0.0f);
            if (sizeof(OutT) == 2) {
                __half2* o0 = (__half2*)((__half*)out + (size_t)(rbase + gid    ) * F2 + col);
                __half2* o1 = (__half2*)((__half*)out + (size_t)(rbase + gid + 8) * F2 + col);
                *o0 = __floats2half2_rn(v00, v01);
                *o1 = __floats2half2_rn(v10, v11);
            } else {
                float2 o0 = {v00, v01}, o1 = {v10, v11};
                *(float2*)((float*)out + (size_t)(rbase + gid    ) * F2 + col) = o0;
                *(float2*)((float*)out + (size_t)(rbase + gid + 8) * F2 + col) = o1;
            }
        }
    }
}

// ---------------- output head ----------------
__global__ void k_out(const float* __restrict__ h2, const float* __restrict__ Wout,
                      const float* __restrict__ bout, float* __restrict__ out) {
    int g = blockIdx.x;
    int t = threadIdx.x;
    const float4* hp = reinterpret_cast<const float4*>(h2 + (size_t)g * (SUB * F2));
    const float4* wp = reinterpret_cast<const float4*>(Wout);
    float s = 0.0f;
    for (int j = t; j < (SUB * F2) / 4; j += 256) {
        float4 hv = hp[j];
        float4 wv = wp[j];
        s += hv.x * wv.x + hv.y * wv.y + hv.z * wv.z + hv.w * wv.w;
    }
#pragma unroll
    for (int off = 16; off > 0; off >>= 1)
        s += __shfl_down_sync(0xFFFFFFFF, s, off);
    __shared__ float sh[8];
    if ((t & 31) == 0) sh[t >> 5] = s;
    __syncthreads();
    if (t < 8) {
        float v = sh[t];
#pragma unroll
        for (int off = 4; off > 0; off >>= 1)
            v += __shfl_down_sync(0xFF, v, off);
        if (t == 0) out[g] = v + bout[0];
    }
}

// ---------------- launch ----------------
extern "C" void kernel_launch(void* const* d_in, const int* in_sizes, int n_in,
                              void* d_out, int out_size) {
    const float* x    = (const float*)d_in[0];
    const void*  ei   = d_in[1];
    const float* W1   = (const float*)d_in[2];
    const float* b1   = (const float*)d_in[3];
    const float* W2   = (const float*)d_in[4];
    const float* b2   = (const float*)d_in[5];
    const float* Wout = (const float*)d_in[6];
    const float* bout = (const float*)d_in[7];
    float* out = (float*)d_out;

    float  *bufA, *bufB, *w1t, *w2t;
    __half *x16, *h16;
    cudaGetSymbolAddress((void**)&bufA, g_bufA);
    cudaGetSymbolAddress((void**)&bufB, g_bufB);
    cudaGetSymbolAddress((void**)&w1t, g_W1t);
    cudaGetSymbolAddress((void**)&w2t, g_W2t);
    cudaGetSymbolAddress((void**)&x16, g_x16);
    cudaGetSymbolAddress((void**)&h16, g_h16);

    // graph build
    k_detect<<<1, 256>>>((const int*)ei);
    k_init_deg<<<NN / 256, 256>>>();
    k_count<<<EE / 256, 256>>>(ei);
    k_dinv<<<NN / 256, 256>>>();
    k_scan1<<<NB_SCAN, SCAN_BS>>>();
    k_scan2<<<1, NB_SCAN>>>();
    k_scan3<<<NB_SCAN, SCAN_BS>>>();
    k_fill<<<EE / 256, 256>>>(ei);

    // weight prep (transpose + tf32 round) + x -> fp16
    k_wt<F1><<<(F1 * 256 + 255) / 256, 256>>>(W1, w1t);
    k_wt<F2><<<(F2 * 256 + 255) / 256, 256>>>(W2, w2t);
    k_f2h<<<(NN * F1 / 4 + 255) / 256, 256>>>(x, x16, NN * F1 / 4);

    // layer 1: aggregate (fp16 gather, 128-wide) then tf32 GEMM -> fp16 h1
    k_agg_h<F1><<<NN, F1 / 2>>>(x16, bufA);
    {
        dim3 grid(F2 / 128, NN / 128);
        k_gemm_mma<F1, __half><<<grid, 256>>>(bufA, w1t, b1, h16);
    }
    // layer 2: aggregate (fp16 gather, 256-wide) then tf32 GEMM -> fp32 h2
    k_agg_h<F2><<<NN, F2 / 2>>>(h16, bufA);
    {
        dim3 grid(F2 / 128, NN / 128);
        k_gemm_mma<F2, float><<<grid, 256>>>(bufA, w2t, b2, bufB);
    }
    // output head
    k_out<<<NG, 256>>>(bufB, Wout, bout, out);
}

// round 5
// speedup vs baseline: 2.7519x; 1.1553x over previous
#include <cuda_runtime.h>
#include <cuda_fp16.h>
#include <cstdint>

// Problem constants (fixed by the dataset)
#define NN 131072          // nodes
#define EE 4194304         // edges
#define F1 128             // input feature dim
#define F2 256             // hidden dim
#define SUB 16             // subgraph group size
#define NG (NN / SUB)      // 8192 output rows
#define SCAN_BS 1024
#define NB_SCAN (NN / SCAN_BS)   // 128

// ---------------- device scratch (static, no allocation) ----------------
__device__ int    g_deg[NN];
__device__ float  g_dinv[NN];
__device__ int    g_ptr[NN + 1];
__device__ int    g_cursor[NN];
__device__ int    g_csrc[EE];
__device__ float  g_cnorm[EE];
__device__ int    g_blockSums[NB_SCAN];
__device__ int    g_edge64;
__device__ __half g_x16[(size_t)NN * F1];    // x in fp16
__device__ __half g_agg[(size_t)NN * F2];    // agg output (fp16) — layer1 uses NN*F1
__device__ __half g_h16[(size_t)NN * F2];    // h1 in fp16
__device__ __half g_h2[(size_t)NN * F2];     // h2 in fp16
__device__ __half g_W1t[(size_t)F2 * F1];    // W1^T fp16  [256 x 128]
__device__ __half g_W2t[(size_t)F2 * F2];    // W2^T fp16  [256 x 256]

__device__ __forceinline__ uint32_t smem_u32(const void* p) {
    return (uint32_t)__cvta_generic_to_shared(p);
}

__device__ __forceinline__ void cp16(uint32_t smem_dst, const void* gsrc) {
    asm volatile("cp.async.cg.shared.global [%0], [%1], 16;"
                 :: "r"(smem_dst), "l"(gsrc));
}
__device__ __forceinline__ void cp_commit() {
    asm volatile("cp.async.commit_group;");
}
template <int N>
__device__ __forceinline__ void cp_wait() {
    asm volatile("cp.async.wait_group %0;" :: "n"(N));
}

// mma.sync m16n8k16 f16 (fp32 accumulate); generic PTX, sm_80+.
__device__ __forceinline__ void mma_f16(float* c, const uint32_t* a, const uint32_t* b) {
    asm volatile(
        "mma.sync.aligned.m16n8k16.row.col.f32.f16.f16.f32 "
        "{%0,%1,%2,%3}, {%4,%5,%6,%7}, {%8,%9}, {%0,%1,%2,%3};"
        : "+f"(c[0]), "+f"(c[1]), "+f"(c[2]), "+f"(c[3])
        : "r"(a[0]), "r"(a[1]), "r"(a[2]), "r"(a[3]),
          "r"(b[0]), "r"(b[1]));
}

// ---------------- edge dtype detection ----------------
// int64 node indices < 2^31 => every odd 32-bit word of the array is 0.
__global__ void k_detect(const int* __restrict__ ei32) {
    int found = 0;
    for (int i = threadIdx.x; i < 4096; i += 256)
        if (ei32[2 * i + 1] != 0) found = 1;
    found = __syncthreads_or(found);
    if (threadIdx.x == 0) g_edge64 = found ? 0 : 1;
}

__device__ __forceinline__ int edge_dst(const void* ei, int e, int is64) {
    if (is64) return (int)((const long long*)ei)[(size_t)EE + e];
    return ((const int*)ei)[(size_t)EE + e];
}
__device__ __forceinline__ int edge_src(const void* ei, int e, int is64) {
    if (is64) return (int)((const long long*)ei)[e];
    return ((const int*)ei)[e];
}

// ---------------- graph normalization / CSR build ----------------
__global__ void k_init_deg() {
    int i = blockIdx.x * blockDim.x + threadIdx.x;
    if (i < NN) g_deg[i] = 1;
}

__global__ void k_count(const void* __restrict__ ei) {
    int e = blockIdx.x * blockDim.x + threadIdx.x;
    if (e >= EE) return;
    atomicAdd(&g_deg[edge_dst(ei, e, g_edge64)], 1);
}

__global__ void k_dinv() {
    int i = blockIdx.x * blockDim.x + threadIdx.x;
    if (i < NN) g_dinv[i] = rsqrtf((float)g_deg[i]);
}

__global__ void k_scan1() {
    __shared__ int sh[2][SCAN_BS];
    int t = threadIdx.x;
    int i = blockIdx.x * SCAN_BS + t;
    int c = g_deg[i] - 1;
    int buf = 0;
    sh[0][t] = c;
    __syncthreads();
#pragma unroll
    for (int off = 1; off < SCAN_BS; off <<= 1) {
        int v = sh[buf][t] + ((t >= off) ? sh[buf][t - off] : 0);
        sh[1 - buf][t] = v;
        buf ^= 1;
        __syncthreads();
    }
    int incl = sh[buf][t];
    g_ptr[i] = incl - c;
    if (t == SCAN_BS - 1) g_blockSums[blockIdx.x] = incl;
}

__global__ void k_scan2() {
    __shared__ int sh[2][NB_SCAN];
    int t = threadIdx.x;
    int c = g_blockSums[t];
    int buf = 0;
    sh[0][t] = c;
    __syncthreads();
#pragma unroll
    for (int off = 1; off < NB_SCAN; off <<= 1) {
        int v = sh[buf][t] + ((t >= off) ? sh[buf][t - off] : 0);
        sh[1 - buf][t] = v;
        buf ^= 1;
        __syncthreads();
    }
    g_blockSums[t] = sh[buf][t] - c;
}

__global__ void k_scan3() {
    int t = threadIdx.x;
    int i = blockIdx.x * SCAN_BS + t;
    int p = g_ptr[i] + g_blockSums[blockIdx.x];
    g_ptr[i] = p;
    g_cursor[i] = p;
    if (i == 0) g_ptr[NN] = EE;
}

__global__ void k_fill(const void* __restrict__ ei) {
    int e = blockIdx.x * blockDim.x + threadIdx.x;
    if (e >= EE) return;
    int is64 = g_edge64;
    int s = edge_src(ei, e, is64);
    int d = edge_dst(ei, e, is64);
    int pos = atomicAdd(&g_cursor[d], 1);
    g_csrc[pos] = s;
    g_cnorm[pos] = g_dinv[s] * g_dinv[d];
}

// ---------------- fp32 -> fp16 conversion (vectorized) ----------------
__global__ void k_f2h(const float* __restrict__ src, __half* __restrict__ dst, int n4) {
    int i = blockIdx.x * blockDim.x + threadIdx.x;   // over n/4
    if (i >= n4) return;
    float4 v = ((const float4*)src)[i];
    ((__half2*)dst)[2 * i    ] = __floats2half2_rn(v.x, v.y);
    ((__half2*)dst)[2 * i + 1] = __floats2half2_rn(v.z, v.w);
}

// ---------------- aggregation on fp16 features, fp32 accumulate, fp16 out ----
// out[i,:] = fp16( sum_{e: dst=i} h[src_e,:]*norm_e + h[i,:]*dinv[i]^2 )
template <int F>
__global__ void k_agg_h(const __half* __restrict__ h, __half* __restrict__ outp) {
    const int T = F / 2;
    int i = blockIdx.x;
    int t = threadIdx.x;
    const __half2* hp = (const __half2*)h;
    float di = g_dinv[i];
    float2 self = __half22float2(hp[(size_t)i * T + t]);
    float ax = self.x * di * di;
    float ay = self.y * di * di;
    int e0 = g_ptr[i], e1 = g_ptr[i + 1];
    __shared__ int   ss[64];
    __shared__ float sn[64];
    for (int base = e0; base < e1; base += 64) {
        int cnt = min(64, e1 - base);
        if (t < cnt) {
            ss[t] = g_csrc[base + t];
            sn[t] = g_cnorm[base + t];
        }
        __syncthreads();
        int j = 0;
        for (; j + 4 <= cnt; j += 4) {
            __half2 v0 = hp[(size_t)ss[j + 0] * T + t];
            __half2 v1 = hp[(size_t)ss[j + 1] * T + t];
            __half2 v2 = hp[(size_t)ss[j + 2] * T + t];
            __half2 v3 = hp[(size_t)ss[j + 3] * T + t];
            float2 f0 = __half22float2(v0);
            float2 f1 = __half22float2(v1);
            float2 f2 = __half22float2(v2);
            float2 f3 = __half22float2(v3);
            ax = fmaf(f0.x, sn[j + 0], ax); ay = fmaf(f0.y, sn[j + 0], ay);
            ax = fmaf(f1.x, sn[j + 1], ax); ay = fmaf(f1.y, sn[j + 1], ay);
            ax = fmaf(f2.x, sn[j + 2], ax); ay = fmaf(f2.y, sn[j + 2], ay);
            ax = fmaf(f3.x, sn[j + 3], ax); ay = fmaf(f3.y, sn[j + 3], ay);
        }
        for (; j < cnt; j++) {
            float2 f = __half22float2(hp[(size_t)ss[j] * T + t]);
            ax = fmaf(f.x, sn[j], ax);
            ay = fmaf(f.y, sn[j], ay);
        }
        __syncthreads();
    }
    ((__half2*)outp)[(size_t)i * T + t] = __floats2half2_rn(ax, ay);
}

// ---------------- weight transpose + fp16 ----------------
// W [K, 256] row-major fp32 -> Wt [256, K] row-major fp16
template <int K>
__global__ void k_wt(const float* __restrict__ W, __half* __restrict__ Wt) {
    int idx = blockIdx.x * blockDim.x + threadIdx.x;   // over K*256
    if (idx >= K * 256) return;
    int k = idx / 256, n = idx % 256;
    Wt[(size_t)n * K + k] = __float2half_rn(W[idx]);
}

// ---------------- fp16 mma.sync GEMM, cp.async double-buffered ----------------
// out[M,256] = relu(A[M,K] @ Wt^T + bias), all fp16 operands, fp32 accumulate.
// CTA: 256 threads, BM=128, BN=128, BK=32, 2 stages. Warp grid 4(M) x 2(N);
// each warp computes 32x64 via m16n8k16 (2 M-tiles x 8 N-tiles x 2 k-steps).
template <int K>
__global__ void __launch_bounds__(256)
k_gemm_h(const __half* __restrict__ A, const __half* __restrict__ Wt,
         const float* __restrict__ bias, __half* __restrict__ out) {
    const int BK = 32, LD = BK + 8;   // LD=40 halves (80B): frag loads conflict-free
    __shared__ __half As[2][128][LD];
    __shared__ __half Bs[2][128][LD];

    int tid = threadIdx.x;
    int lane = tid & 31;
    int warp = tid >> 5;
    int warp_m = warp & 3;       // 0..3
    int warp_n = warp >> 2;      // 0..1
    int gid = lane >> 2;         // 0..7
    int tig = lane & 3;          // 0..3
    int m0 = blockIdx.y * 128;
    int n0 = blockIdx.x * 128;

    float c[2][8][4];
#pragma unroll
    for (int mm = 0; mm < 2; mm++)
#pragma unroll
        for (int nn = 0; nn < 8; nn++)
#pragma unroll
            for (int q = 0; q < 4; q++) c[mm][nn][q] = 0.0f;

    // staging: 128 rows x 4 cp16 chunks (64B/row) per tile; 2 per thread per tile
    int srow0 = tid >> 2, sc0 = (tid & 3) * 8;            // half offsets
    int srow1 = (tid + 256) >> 2, sc1 = sc0;
    const int NCH = K / BK;

    {   // prefetch chunk 0 into buf 0
        cp16(smem_u32(&As[0][srow0][sc0]), &A[(size_t)(m0 + srow0) * K + sc0]);
        cp16(smem_u32(&Bs[0][srow0][sc0]), &Wt[(size_t)(n0 + srow0) * K + sc0]);
        cp16(smem_u32(&As[0][srow1][sc1]), &A[(size_t)(m0 + srow1) * K + sc1]);
        cp16(smem_u32(&Bs[0][srow1][sc1]), &Wt[(size_t)(n0 + srow1) * K + sc1]);
        cp_commit();
    }

#pragma unroll
    for (int ch = 0; ch < NCH; ch++) {
        int buf = ch & 1;
        if (ch + 1 < NCH) {
            int nb = buf ^ 1, kofs = (ch + 1) * BK;
            cp16(smem_u32(&As[nb][srow0][sc0]), &A[(size_t)(m0 + srow0) * K + kofs + sc0]);
            cp16(smem_u32(&Bs[nb][srow0][sc0]), &Wt[(size_t)(n0 + srow0) * K + kofs + sc0]);
            cp16(smem_u32(&As[nb][srow1][sc1]), &A[(size_t)(m0 + srow1) * K + kofs + sc1]);
            cp16(smem_u32(&Bs[nb][srow1][sc1]), &Wt[(size_t)(n0 + srow1) * K + kofs + sc1]);
        }
        cp_commit();
        cp_wait<1>();
        __syncthreads();

#pragma unroll
        for (int kk = 0; kk < 2; kk++) {
            int kb = kk * 16;
            uint32_t a[2][4], b[8][2];
#pragma unroll
            for (int mm = 0; mm < 2; mm++) {
                int r = warp_m * 32 + mm * 16;
                a[mm][0] = *(const uint32_t*)&As[buf][r + gid    ][kb + 2 * tig    ];
                a[mm][1] = *(const uint32_t*)&As[buf][r + gid + 8][kb + 2 * tig    ];
                a[mm][2] = *(const uint32_t*)&As[buf][r + gid    ][kb + 2 * tig + 8];
                a[mm][3] = *(const uint32_t*)&As[buf][r + gid + 8][kb + 2 * tig + 8];
            }
#pragma unroll
            for (int nn = 0; nn < 8; nn++) {
                int r = warp_n * 64 + nn * 8;
                b[nn][0] = *(const uint32_t*)&Bs[buf][r + gid][kb + 2 * tig    ];
                b[nn][1] = *(const uint32_t*)&Bs[buf][r + gid][kb + 2 * tig + 8];
            }
#pragma unroll
            for (int mm = 0; mm < 2; mm++)
#pragma unroll
                for (int nn = 0; nn < 8; nn++)
                    mma_f16(c[mm][nn], a[mm], b[nn]);
        }
        __syncthreads();
    }

    // epilogue: bias + relu -> fp16
#pragma unroll
    for (int mm = 0; mm < 2; mm++) {
        int rbase = m0 + warp_m * 32 + mm * 16;
#pragma unroll
        for (int nn = 0; nn < 8; nn++) {
            int col = n0 + warp_n * 64 + nn * 8 + tig * 2;
            float bi0 = bias[col], bi1 = bias[col + 1];
            float v00 = fmaxf(c[mm][nn][0] + bi0, 0.0f);
            float v01 = fmaxf(c[mm][nn][1] + bi1, 0.0f);
            float v10 = fmaxf(c[mm][nn][2] + bi0, 0.0f);
            float v11 = fmaxf(c[mm][nn][3] + bi1, 0.0f);
            *(__half2*)&out[(size_t)(rbase + gid    ) * F2 + col] = __floats2half2_rn(v00, v01);
            *(__half2*)&out[(size_t)(rbase + gid + 8) * F2 + col] = __floats2half2_rn(v10, v11);
        }
    }
}

// ---------------- output head (fp16 h2, fp32 weights/accum) ----------------
__global__ void k_out(const __half* __restrict__ h2, const float* __restrict__ Wout,
                      const float* __restrict__ bout, float* __restrict__ out) {
    int g = blockIdx.x;
    int t = threadIdx.x;
    const __half2* hp = (const __half2*)(h2 + (size_t)g * (SUB * F2));
    const float2* wp = (const float2*)Wout;
    float s = 0.0f;
    for (int j = t; j < (SUB * F2) / 2; j += 256) {
        float2 h = __half22float2(hp[j]);
        float2 w = wp[j];
        s += h.x * w.x + h.y * w.y;
    }
#pragma unroll
    for (int off = 16; off > 0; off >>= 1)
        s += __shfl_down_sync(0xFFFFFFFF, s, off);
    __shared__ float sh[8];
    if ((t & 31) == 0) sh[t >> 5] = s;
    __syncthreads();
    if (t < 8) {
        float v = sh[t];
#pragma unroll
        for (int off = 4; off > 0; off >>= 1)
            v += __shfl_down_sync(0xFF, v, off);
        if (t == 0) out[g] = v + bout[0];
    }
}

// ---------------- launch ----------------
extern "C" void kernel_launch(void* const* d_in, const int* in_sizes, int n_in,
                              void* d_out, int out_size) {
    const float* x    = (const float*)d_in[0];
    const void*  ei   = d_in[1];
    const float* W1   = (const float*)d_in[2];
    const float* b1   = (const float*)d_in[3];
    const float* W2   = (const float*)d_in[4];
    const float* b2   = (const float*)d_in[5];
    const float* Wout = (const float*)d_in[6];
    const float* bout = (const float*)d_in[7];
    float* out = (float*)d_out;

    __half *x16, *agg, *h16, *h2, *w1t, *w2t;
    cudaGetSymbolAddress((void**)&x16, g_x16);
    cudaGetSymbolAddress((void**)&agg, g_agg);
    cudaGetSymbolAddress((void**)&h16, g_h16);
    cudaGetSymbolAddress((void**)&h2,  g_h2);
    cudaGetSymbolAddress((void**)&w1t, g_W1t);
    cudaGetSymbolAddress((void**)&w2t, g_W2t);

    // graph build
    k_detect<<<1, 256>>>((const int*)ei);
    k_init_deg<<<NN / 256, 256>>>();
    k_count<<<EE / 256, 256>>>(ei);
    k_dinv<<<NN / 256, 256>>>();
    k_scan1<<<NB_SCAN, SCAN_BS>>>();
    k_scan2<<<1, NB_SCAN>>>();
    k_scan3<<<NB_SCAN, SCAN_BS>>>();
    k_fill<<<EE / 256, 256>>>(ei);

    // weight prep (transpose + fp16) + x -> fp16
    k_wt<F1><<<(F1 * 256 + 255) / 256, 256>>>(W1, w1t);
    k_wt<F2><<<(F2 * 256 + 255) / 256, 256>>>(W2, w2t);
    k_f2h<<<(NN * F1 / 4 + 255) / 256, 256>>>(x, x16, NN * F1 / 4);

    // layer 1: aggregate (fp16, 128-wide) then fp16 GEMM -> fp16 h1
    k_agg_h<F1><<<NN, F1 / 2>>>(x16, agg);
    {
        dim3 grid(F2 / 128, NN / 128);
        k_gemm_h<F1><<<grid, 256>>>(agg, w1t, b1, h16);
    }
    // layer 2: aggregate (fp16, 256-wide) then fp16 GEMM -> fp16 h2
    k_agg_h<F2><<<NN, F2 / 2>>>(h16, agg);
    {
        dim3 grid(F2 / 128, NN / 128);
        k_gemm_h<F2><<<grid, 256>>>(agg, w2t, b2, h2);
    }
    // output head
    k_out<<<NG, 256>>>(h2, Wout, bout, out);
}

// round 6
// speedup vs baseline: 3.5160x; 1.2777x over previous
#include <cuda_runtime.h>
#include <cuda_fp16.h>
#include <cstdint>

// Problem constants (fixed by the dataset)
#define NN 131072          // nodes
#define EE 4194304         // edges
#define F1 128             // input feature dim
#define F2 256             // hidden dim
#define SUB 16             // subgraph group size
#define NG (NN / SUB)      // 8192 output rows
#define SCAN_BS 1024
#define NB_SCAN (NN / SCAN_BS)   // 128

// ---------------- device scratch (static, no allocation) ----------------
__device__ int    g_deg[NN];
__device__ float  g_dinv[NN];
__device__ int    g_ptr[NN + 1];
__device__ int    g_cursor[NN];
__device__ int    g_csrc[EE];
__device__ int    g_blockSums[NB_SCAN];
__device__ int    g_edge64;
__device__ __half g_x16[(size_t)NN * F1];    // x in fp16
__device__ __half g_agg[(size_t)NN * F2];    // agg output (fp16)
__device__ __half g_h16[(size_t)NN * F2];    // h1 in fp16
__device__ __half g_W1t[(size_t)F2 * F1];    // W1^T fp16  [256 x 128]
__device__ __half g_W2t[(size_t)F2 * F2];    // W2^T fp16  [256 x 256]
__device__ float  g_part[(size_t)NG * 4];    // fused-head partials

__device__ __forceinline__ uint32_t smem_u32(const void* p) {
    return (uint32_t)__cvta_generic_to_shared(p);
}

__device__ __forceinline__ void cp16(uint32_t smem_dst, const void* gsrc) {
    asm volatile("cp.async.cg.shared.global [%0], [%1], 16;"
                 :: "r"(smem_dst), "l"(gsrc));
}
__device__ __forceinline__ void cp_commit() {
    asm volatile("cp.async.commit_group;");
}
template <int N>
__device__ __forceinline__ void cp_wait() {
    asm volatile("cp.async.wait_group %0;" :: "n"(N));
}

// mma.sync m16n8k16 f16 (fp32 accumulate); generic PTX, sm_80+.
__device__ __forceinline__ void mma_f16(float* c, const uint32_t* a, const uint32_t* b) {
    asm volatile(
        "mma.sync.aligned.m16n8k16.row.col.f32.f16.f16.f32 "
        "{%0,%1,%2,%3}, {%4,%5,%6,%7}, {%8,%9}, {%0,%1,%2,%3};"
        : "+f"(c[0]), "+f"(c[1]), "+f"(c[2]), "+f"(c[3])
        : "r"(a[0]), "r"(a[1]), "r"(a[2]), "r"(a[3]),
          "r"(b[0]), "r"(b[1]));
}

// vectorized row-slice load/store of V half2 (V = 2 or 4)
template <int V> struct RowV { __half2 v[V]; };
template <int V>
__device__ __forceinline__ RowV<V> ldrow(const __half2* p) {
    RowV<V> r;
    if (V == 2) {
        uint2 u = *(const uint2*)p;
        r.v[0] = *(__half2*)&u.x; r.v[1] = *(__half2*)&u.y;
    } else {
        uint4 u = *(const uint4*)p;
        r.v[0] = *(__half2*)&u.x; r.v[1] = *(__half2*)&u.y;
        r.v[2] = *(__half2*)&u.z; r.v[3] = *(__half2*)&u.w;
    }
    return r;
}
template <int V>
__device__ __forceinline__ void strow(__half2* p, const RowV<V>& r) {
    if (V == 2) {
        uint2 u;
        u.x = *(const uint32_t*)&r.v[0]; u.y = *(const uint32_t*)&r.v[1];
        *(uint2*)p = u;
    } else {
        uint4 u;
        u.x = *(const uint32_t*)&r.v[0]; u.y = *(const uint32_t*)&r.v[1];
        u.z = *(const uint32_t*)&r.v[2]; u.w = *(const uint32_t*)&r.v[3];
        *(uint4*)p = u;
    }
}

// ---------------- edge dtype detection ----------------
// int64 node indices < 2^31 => every odd 32-bit word of the array is 0.
__global__ void k_detect(const int* __restrict__ ei32) {
    int found = 0;
    for (int i = threadIdx.x; i < 4096; i += 256)
        if (ei32[2 * i + 1] != 0) found = 1;
    found = __syncthreads_or(found);
    if (threadIdx.x == 0) g_edge64 = found ? 0 : 1;
}

__device__ __forceinline__ int edge_dst(const void* ei, int e, int is64) {
    if (is64) return (int)((const long long*)ei)[(size_t)EE + e];
    return ((const int*)ei)[(size_t)EE + e];
}
__device__ __forceinline__ int edge_src(const void* ei, int e, int is64) {
    if (is64) return (int)((const long long*)ei)[e];
    return ((const int*)ei)[e];
}

// ---------------- graph normalization / CSR build ----------------
__global__ void k_init_deg() {
    int i = blockIdx.x * blockDim.x + threadIdx.x;
    if (i < NN) g_deg[i] = 1;
}

__global__ void k_count(const void* __restrict__ ei) {
    int e = blockIdx.x * blockDim.x + threadIdx.x;
    if (e >= EE) return;
    atomicAdd(&g_deg[edge_dst(ei, e, g_edge64)], 1);
}

__global__ void k_dinv() {
    int i = blockIdx.x * blockDim.x + threadIdx.x;
    if (i < NN) g_dinv[i] = rsqrtf((float)g_deg[i]);
}

__global__ void k_scan1() {
    __shared__ int sh[2][SCAN_BS];
    int t = threadIdx.x;
    int i = blockIdx.x * SCAN_BS + t;
    int c = g_deg[i] - 1;
    int buf = 0;
    sh[0][t] = c;
    __syncthreads();
#pragma unroll
    for (int off = 1; off < SCAN_BS; off <<= 1) {
        int v = sh[buf][t] + ((t >= off) ? sh[buf][t - off] : 0);
        sh[1 - buf][t] = v;
        buf ^= 1;
        __syncthreads();
    }
    int incl = sh[buf][t];
    g_ptr[i] = incl - c;
    if (t == SCAN_BS - 1) g_blockSums[blockIdx.x] = incl;
}

__global__ void k_scan2() {
    __shared__ int sh[2][NB_SCAN];
    int t = threadIdx.x;
    int c = g_blockSums[t];
    int buf = 0;
    sh[0][t] = c;
    __syncthreads();
#pragma unroll
    for (int off = 1; off < NB_SCAN; off <<= 1) {
        int v = sh[buf][t] + ((t >= off) ? sh[buf][t - off] : 0);
        sh[1 - buf][t] = v;
        buf ^= 1;
        __syncthreads();
    }
    g_blockSums[t] = sh[buf][t] - c;
}

__global__ void k_scan3() {
    int t = threadIdx.x;
    int i = blockIdx.x * SCAN_BS + t;
    int p = g_ptr[i] + g_blockSums[blockIdx.x];
    g_ptr[i] = p;
    g_cursor[i] = p;
    if (i == 0) g_ptr[NN] = EE;
}

__global__ void k_fill(const void* __restrict__ ei) {
    int e = blockIdx.x * blockDim.x + threadIdx.x;
    if (e >= EE) return;
    int is64 = g_edge64;
    int s = edge_src(ei, e, is64);
    int d = edge_dst(ei, e, is64);
    int pos = atomicAdd(&g_cursor[d], 1);
    g_csrc[pos] = s;
}

// ---------------- fp32 -> fp16 conversion (vectorized) ----------------
__global__ void k_f2h(const float* __restrict__ src, __half* __restrict__ dst, int n4) {
    int i = blockIdx.x * blockDim.x + threadIdx.x;   // over n/4
    if (i >= n4) return;
    float4 v = ((const float4*)src)[i];
    ((__half2*)dst)[2 * i    ] = __floats2half2_rn(v.x, v.y);
    ((__half2*)dst)[2 * i + 1] = __floats2half2_rn(v.z, v.w);
}

// ---------------- warp-per-node aggregation ----------------
// out[i,:] = fp16( sum_{e: dst=i} h[src_e,:]*dinv[src]*dinv[i] + h[i,:]*dinv[i]^2 )
// One warp per node; each lane owns V = F/64 half2 columns (8B or 16B slice).
template <int F>
__global__ void __launch_bounds__(256)
k_agg_w(const __half* __restrict__ h, __half* __restrict__ outp) {
    const int T = F / 2;          // half2 per row
    const int V = T / 32;         // half2 per lane: 2 (F1) or 4 (F2)
    int gw = (blockIdx.x * 256 + threadIdx.x) >> 5;    // node id
    int lane = threadIdx.x & 31;
    int i = gw;
    const __half2* base = (const __half2*)h;
    const __half2* self = base + (size_t)i * T + lane * V;
    float di = g_dinv[i];

    float acc[2 * V];
    {
        RowV<V> r = ldrow<V>(self);
        float dsq = di * di;
#pragma unroll
        for (int v = 0; v < V; v++) {
            float2 f = __half22float2(r.v[v]);
            acc[2 * v    ] = f.x * dsq;
            acc[2 * v + 1] = f.y * dsq;
        }
    }

    int e0 = g_ptr[i], e1 = g_ptr[i + 1];
    int e = e0;
    for (; e + 4 <= e1; e += 4) {
        int s0 = g_csrc[e    ], s1 = g_csrc[e + 1];
        int s2 = g_csrc[e + 2], s3 = g_csrc[e + 3];
        float w0 = g_dinv[s0] * di, w1 = g_dinv[s1] * di;
        float w2 = g_dinv[s2] * di, w3 = g_dinv[s3] * di;
        RowV<V> r0 = ldrow<V>(base + (size_t)s0 * T + lane * V);
        RowV<V> r1 = ldrow<V>(base + (size_t)s1 * T + lane * V);
        RowV<V> r2 = ldrow<V>(base + (size_t)s2 * T + lane * V);
        RowV<V> r3 = ldrow<V>(base + (size_t)s3 * T + lane * V);
#pragma unroll
        for (int v = 0; v < V; v++) {
            float2 f0 = __half22float2(r0.v[v]);
            float2 f1 = __half22float2(r1.v[v]);
            float2 f2 = __half22float2(r2.v[v]);
            float2 f3 = __half22float2(r3.v[v]);
            acc[2 * v    ] = fmaf(f0.x, w0, acc[2 * v    ]);
            acc[2 * v + 1] = fmaf(f0.y, w0, acc[2 * v + 1]);
            acc[2 * v    ] = fmaf(f1.x, w1, acc[2 * v    ]);
            acc[2 * v + 1] = fmaf(f1.y, w1, acc[2 * v + 1]);
            acc[2 * v    ] = fmaf(f2.x, w2, acc[2 * v    ]);
            acc[2 * v + 1] = fmaf(f2.y, w2, acc[2 * v + 1]);
            acc[2 * v    ] = fmaf(f3.x, w3, acc[2 * v    ]);
            acc[2 * v + 1] = fmaf(f3.y, w3, acc[2 * v + 1]);
        }
    }
    for (; e < e1; e++) {
        int s = g_csrc[e];
        float w = g_dinv[s] * di;
        RowV<V> r = ldrow<V>(base + (size_t)s * T + lane * V);
#pragma unroll
        for (int v = 0; v < V; v++) {
            float2 f = __half22float2(r.v[v]);
            acc[2 * v    ] = fmaf(f.x, w, acc[2 * v    ]);
            acc[2 * v + 1] = fmaf(f.y, w, acc[2 * v + 1]);
        }
    }

    RowV<V> o;
#pragma unroll
    for (int v = 0; v < V; v++)
        o.v[v] = __floats2half2_rn(acc[2 * v], acc[2 * v + 1]);
    strow<V>((__half2*)outp + (size_t)i * T + lane * V, o);
}

// ---------------- weight transpose + fp16 ----------------
// W [K, 256] row-major fp32 -> Wt [256, K] row-major fp16
template <int K>
__global__ void k_wt(const float* __restrict__ W, __half* __restrict__ Wt) {
    int idx = blockIdx.x * blockDim.x + threadIdx.x;   // over K*256
    if (idx >= K * 256) return;
    int k = idx / 256, n = idx % 256;
    Wt[(size_t)n * K + k] = __float2half_rn(W[idx]);
}

// ---------------- fp16 mma.sync GEMM, cp.async double-buffered ----------------
// out[M,256] = relu(A[M,K] @ Wt^T + bias) -> fp16.
template <int K>
__global__ void __launch_bounds__(256)
k_gemm_h(const __half* __restrict__ A, const __half* __restrict__ Wt,
         const float* __restrict__ bias, __half* __restrict__ out) {
    const int BK = 32, LD = BK + 8;
    __shared__ __half As[2][128][LD];
    __shared__ __half Bs[2][128][LD];

    int tid = threadIdx.x;
    int lane = tid & 31;
    int warp = tid >> 5;
    int warp_m = warp & 3;
    int warp_n = warp >> 2;
    int gid = lane >> 2;
    int tig = lane & 3;
    int m0 = blockIdx.y * 128;
    int n0 = blockIdx.x * 128;

    float c[2][8][4];
#pragma unroll
    for (int mm = 0; mm < 2; mm++)
#pragma unroll
        for (int nn = 0; nn < 8; nn++)
#pragma unroll
            for (int q = 0; q < 4; q++) c[mm][nn][q] = 0.0f;

    int srow0 = tid >> 2, sc0 = (tid & 3) * 8;
    int srow1 = (tid + 256) >> 2, sc1 = sc0;
    const int NCH = K / BK;

    cp16(smem_u32(&As[0][srow0][sc0]), &A[(size_t)(m0 + srow0) * K + sc0]);
    cp16(smem_u32(&Bs[0][srow0][sc0]), &Wt[(size_t)(n0 + srow0) * K + sc0]);
    cp16(smem_u32(&As[0][srow1][sc1]), &A[(size_t)(m0 + srow1) * K + sc1]);
    cp16(smem_u32(&Bs[0][srow1][sc1]), &Wt[(size_t)(n0 + srow1) * K + sc1]);
    cp_commit();

#pragma unroll
    for (int ch = 0; ch < NCH; ch++) {
        int buf = ch & 1;
        if (ch + 1 < NCH) {
            int nb = buf ^ 1, kofs = (ch + 1) * BK;
            cp16(smem_u32(&As[nb][srow0][sc0]), &A[(size_t)(m0 + srow0) * K + kofs + sc0]);
            cp16(smem_u32(&Bs[nb][srow0][sc0]), &Wt[(size_t)(n0 + srow0) * K + kofs + sc0]);
            cp16(smem_u32(&As[nb][srow1][sc1]), &A[(size_t)(m0 + srow1) * K + kofs + sc1]);
            cp16(smem_u32(&Bs[nb][srow1][sc1]), &Wt[(size_t)(n0 + srow1) * K + kofs + sc1]);
        }
        cp_commit();
        cp_wait<1>();
        __syncthreads();

#pragma unroll
        for (int kk = 0; kk < 2; kk++) {
            int kb = kk * 16;
            uint32_t a[2][4], b[8][2];
#pragma unroll
            for (int mm = 0; mm < 2; mm++) {
                int r = warp_m * 32 + mm * 16;
                a[mm][0] = *(const uint32_t*)&As[buf][r + gid    ][kb + 2 * tig    ];
                a[mm][1] = *(const uint32_t*)&As[buf][r + gid + 8][kb + 2 * tig    ];
                a[mm][2] = *(const uint32_t*)&As[buf][r + gid    ][kb + 2 * tig + 8];
                a[mm][3] = *(const uint32_t*)&As[buf][r + gid + 8][kb + 2 * tig + 8];
            }
#pragma unroll
            for (int nn = 0; nn < 8; nn++) {
                int r = warp_n * 64 + nn * 8;
                b[nn][0] = *(const uint32_t*)&Bs[buf][r + gid][kb + 2 * tig    ];
                b[nn][1] = *(const uint32_t*)&Bs[buf][r + gid][kb + 2 * tig + 8];
            }
#pragma unroll
            for (int mm = 0; mm < 2; mm++)
#pragma unroll
                for (int nn = 0; nn < 8; nn++)
                    mma_f16(c[mm][nn], a[mm], b[nn]);
        }
        __syncthreads();
    }

#pragma unroll
    for (int mm = 0; mm < 2; mm++) {
        int rbase = m0 + warp_m * 32 + mm * 16;
#pragma unroll
        for (int nn = 0; nn < 8; nn++) {
            int col = n0 + warp_n * 64 + nn * 8 + tig * 2;
            float bi0 = bias[col], bi1 = bias[col + 1];
            float v00 = fmaxf(c[mm][nn][0] + bi0, 0.0f);
            float v01 = fmaxf(c[mm][nn][1] + bi1, 0.0f);
            float v10 = fmaxf(c[mm][nn][2] + bi0, 0.0f);
            float v11 = fmaxf(c[mm][nn][3] + bi1, 0.0f);
            *(__half2*)&out[(size_t)(rbase + gid    ) * F2 + col] = __floats2half2_rn(v00, v01);
            *(__half2*)&out[(size_t)(rbase + gid + 8) * F2 + col] = __floats2half2_rn(v10, v11);
        }
    }
}

// ---------------- layer-2 GEMM with fused output head ----------------
// Computes h2 = relu(A @ W2^T + b2) in registers, then per-thread dot with
// Wout[(row&15)*256 + col], warp-reduced, written as deterministic partials:
// g_part[group*4 + (blockIdx.x*2 + warp_n)].
template <int K>
__global__ void __launch_bounds__(256)
k_gemm_fin(const __half* __restrict__ A, const __half* __restrict__ Wt,
           const float* __restrict__ bias, const float* __restrict__ Wout) {
    const int BK = 32, LD = BK + 8;
    __shared__ __half As[2][128][LD];
    __shared__ __half Bs[2][128][LD];

    int tid = threadIdx.x;
    int lane = tid & 31;
    int warp = tid >> 5;
    int warp_m = warp & 3;
    int warp_n = warp >> 2;
    int gid = lane >> 2;
    int tig = lane & 3;
    int m0 = blockIdx.y * 128;
    int n0 = blockIdx.x * 128;

    float c[2][8][4];
#pragma unroll
    for (int mm = 0; mm < 2; mm++)
#pragma unroll
        for (int nn = 0; nn < 8; nn++)
#pragma unroll
            for (int q = 0; q < 4; q++) c[mm][nn][q] = 0.0f;

    int srow0 = tid >> 2, sc0 = (tid & 3) * 8;
    int srow1 = (tid + 256) >> 2, sc1 = sc0;
    const int NCH = K / BK;

    cp16(smem_u32(&As[0][srow0][sc0]), &A[(size_t)(m0 + srow0) * K + sc0]);
    cp16(smem_u32(&Bs[0][srow0][sc0]), &Wt[(size_t)(n0 + srow0) * K + sc0]);
    cp16(smem_u32(&As[0][srow1][sc1]), &A[(size_t)(m0 + srow1) * K + sc1]);
    cp16(smem_u32(&Bs[0][srow1][sc1]), &Wt[(size_t)(n0 + srow1) * K + sc1]);
    cp_commit();

#pragma unroll
    for (int ch = 0; ch < NCH; ch++) {
        int buf = ch & 1;
        if (ch + 1 < NCH) {
            int nb = buf ^ 1, kofs = (ch + 1) * BK;
            cp16(smem_u32(&As[nb][srow0][sc0]), &A[(size_t)(m0 + srow0) * K + kofs + sc0]);
            cp16(smem_u32(&Bs[nb][srow0][sc0]), &Wt[(size_t)(n0 + srow0) * K + kofs + sc0]);
            cp16(smem_u32(&As[nb][srow1][sc1]), &A[(size_t)(m0 + srow1) * K + kofs + sc1]);
            cp16(smem_u32(&Bs[nb][srow1][sc1]), &Wt[(size_t)(n0 + srow1) * K + kofs + sc1]);
        }
        cp_commit();
        cp_wait<1>();
        __syncthreads();

#pragma unroll
        for (int kk = 0; kk < 2; kk++) {
            int kb = kk * 16;
            uint32_t a[2][4], b[8][2];
#pragma unroll
            for (int mm = 0; mm < 2; mm++) {
                int r = warp_m * 32 + mm * 16;
                a[mm][0] = *(const uint32_t*)&As[buf][r + gid    ][kb + 2 * tig    ];
                a[mm][1] = *(const uint32_t*)&As[buf][r + gid + 8][kb + 2 * tig    ];
                a[mm][2] = *(const uint32_t*)&As[buf][r + gid    ][kb + 2 * tig + 8];
                a[mm][3] = *(const uint32_t*)&As[buf][r + gid + 8][kb + 2 * tig + 8];
            }
#pragma unroll
            for (int nn = 0; nn < 8; nn++) {
                int r = warp_n * 64 + nn * 8;
                b[nn][0] = *(const uint32_t*)&Bs[buf][r + gid][kb + 2 * tig    ];
                b[nn][1] = *(const uint32_t*)&Bs[buf][r + gid][kb + 2 * tig + 8];
            }
#pragma unroll
            for (int mm = 0; mm < 2; mm++)
#pragma unroll
                for (int nn = 0; nn < 8; nn++)
                    mma_f16(c[mm][nn], a[mm], b[nn]);
        }
        __syncthreads();
    }

    // fused epilogue: relu(c + bias) dot Wout[(row&15)*256 + col]
    float vsum[2] = {0.0f, 0.0f};
#pragma unroll
    for (int mm = 0; mm < 2; mm++) {
#pragma unroll
        for (int nn = 0; nn < 8; nn++) {
            int col = n0 + warp_n * 64 + nn * 8 + tig * 2;
            float bi0 = bias[col], bi1 = bias[col + 1];
            float v00 = fmaxf(c[mm][nn][0] + bi0, 0.0f);
            float v01 = fmaxf(c[mm][nn][1] + bi1, 0.0f);
            float v10 = fmaxf(c[mm][nn][2] + bi0, 0.0f);
            float v11 = fmaxf(c[mm][nn][3] + bi1, 0.0f);
            // rows rbase+gid and rbase+gid+8; (row & 15) = gid and gid+8
            float w00 = Wout[gid * 256 + col];
            float w01 = Wout[gid * 256 + col + 1];
            float w10 = Wout[(gid + 8) * 256 + col];
            float w11 = Wout[(gid + 8) * 256 + col + 1];
            vsum[mm] += v00 * w00 + v01 * w01 + v10 * w10 + v11 * w11;
        }
    }
#pragma unroll
    for (int off = 16; off > 0; off >>= 1) {
        vsum[0] += __shfl_down_sync(0xFFFFFFFF, vsum[0], off);
        vsum[1] += __shfl_down_sync(0xFFFFFFFF, vsum[1], off);
    }
    if (lane == 0) {
        int quarter = blockIdx.x * 2 + warp_n;
#pragma unroll
        for (int mm = 0; mm < 2; mm++) {
            int group = (m0 >> 4) + warp_m * 2 + mm;
            g_part[(size_t)group * 4 + quarter] = vsum[mm];
        }
    }
}

// ---------------- finisher: sum 4 partials + bias ----------------
__global__ void k_fin(const float* __restrict__ bout, float* __restrict__ out) {
    int g = blockIdx.x * blockDim.x + threadIdx.x;
    if (g >= NG) return;
    float4 p = *(const float4*)&g_part[(size_t)g * 4];
    out[g] = p.x + p.y + p.z + p.w + bout[0];
}

// ---------------- launch ----------------
extern "C" void kernel_launch(void* const* d_in, const int* in_sizes, int n_in,
                              void* d_out, int out_size) {
    const float* x    = (const float*)d_in[0];
    const void*  ei   = d_in[1];
    const float* W1   = (const float*)d_in[2];
    const float* b1   = (const float*)d_in[3];
    const float* W2   = (const float*)d_in[4];
    const float* b2   = (const float*)d_in[5];
    const float* Wout = (const float*)d_in[6];
    const float* bout = (const float*)d_in[7];
    float* out = (float*)d_out;

    __half *x16, *agg, *h16, *w1t, *w2t;
    cudaGetSymbolAddress((void**)&x16, g_x16);
    cudaGetSymbolAddress((void**)&agg, g_agg);
    cudaGetSymbolAddress((void**)&h16, g_h16);
    cudaGetSymbolAddress((void**)&w1t, g_W1t);
    cudaGetSymbolAddress((void**)&w2t, g_W2t);

    // graph build
    k_detect<<<1, 256>>>((const int*)ei);
    k_init_deg<<<NN / 256, 256>>>();
    k_count<<<EE / 256, 256>>>(ei);
    k_dinv<<<NN / 256, 256>>>();
    k_scan1<<<NB_SCAN, SCAN_BS>>>();
    k_scan2<<<1, NB_SCAN>>>();
    k_scan3<<<NB_SCAN, SCAN_BS>>>();
    k_fill<<<EE / 256, 256>>>(ei);

    // weight prep (transpose + fp16) + x -> fp16
    k_wt<F1><<<(F1 * 256 + 255) / 256, 256>>>(W1, w1t);
    k_wt<F2><<<(F2 * 256 + 255) / 256, 256>>>(W2, w2t);
    k_f2h<<<(NN * F1 / 4 + 255) / 256, 256>>>(x, x16, NN * F1 / 4);

    // layer 1: warp-per-node aggregate then fp16 GEMM -> fp16 h1
    k_agg_w<F1><<<NN * 32 / 256, 256>>>(x16, agg);
    {
        dim3 grid(F2 / 128, NN / 128);
        k_gemm_h<F1><<<grid, 256>>>(agg, w1t, b1, h16);
    }
    // layer 2: warp-per-node aggregate then fp16 GEMM fused with output head
    k_agg_w<F2><<<NN * 32 / 256, 256>>>(h16, agg);
    {
        dim3 grid(F2 / 128, NN / 128);
        k_gemm_fin<F2><<<grid, 256>>>(agg, w2t, b2, Wout);
    }
    // finisher
    k_fin<<<NG / 256, 256>>>(bout, out);
}